// round 2
// baseline (speedup 1.0000x reference)
#include <cuda_runtime.h>
#include <math.h>

// ---------------- problem constants ----------------
#define BB 4
#define HH 480
#define WW 640
#define HWW (HH*WW)          // 307200
#define BHW (BB*HWW)         // 1228800
#define RAD 4
#define THR 0.005f
#define MAXKP 1024
#define CAP 16384            // max candidates per batch (hard bound ~12288)
#define NBUCK 4096
#define SELCAP 2048
#define KTOT 704

// feature maps
#define C1 64
#define H1 240
#define W1 320
#define C2 128
#define H2 120
#define W2 160
#define C3 256
#define H3 60
#define W3 80
#define C4 256
#define H4 30
#define W4 40

// ---------------- scratch ----------------
__device__ float              g_tmpA[BHW];
__device__ unsigned char      g_maxmask[BHW];
__device__ unsigned char      g_supp[BHW];
__device__ unsigned char      g_tmpm[BHW];
__device__ unsigned long long g_cand[BB*CAP];
__device__ int                g_count[BB];
__device__ int                g_hist[BB*NBUCK];
__device__ int                g_selidx[BB*MAXKP];
__device__ float              g_X[(size_t)BB*MAXKP*KTOT];   // normalized sampled descriptors
__device__ float              g_M[256*KTOT];                // folded merge weights
__device__ float              g_bias[256];                  // folded bias

// ---------------- weight folding ----------------
__global__ void k_fold(const float* __restrict__ mw,
                       const float* __restrict__ l0w, const float* __restrict__ l1w,
                       const float* __restrict__ l2w)
{
    int t = blockIdx.x*blockDim.x + threadIdx.x;
    if (t >= 256*KTOT) return;
    int o = t / KTOT, i = t % KTOT;
    const float* mrow = mw + o*KTOT;
    float acc = 0.f;
    if (i < 64) {
        for (int j = 0; j < 64; j++)  acc += mrow[j]       * l2w[j*64  + i];
    } else if (i < 192) {
        int ii = i - 64;
        for (int j = 0; j < 128; j++) acc += mrow[64 + j]  * l1w[j*128 + ii];
    } else if (i < 448) {
        acc = mrow[i];
    } else {
        int ii = i - 448;
        for (int j = 0; j < 256; j++) acc += mrow[448 + j] * l0w[j*256 + ii];
    }
    g_M[t] = acc;
}

__global__ void k_foldbias(const float* __restrict__ mw, const float* __restrict__ mb,
                           const float* __restrict__ l0b, const float* __restrict__ l1b,
                           const float* __restrict__ l2b)
{
    int o = threadIdx.x;   // 256 threads
    const float* mrow = mw + o*KTOT;
    float acc = mb[o];
    for (int j = 0; j < 64;  j++) acc += mrow[j]       * l2b[j];
    for (int j = 0; j < 128; j++) acc += mrow[64 + j]  * l1b[j];
    for (int j = 0; j < 256; j++) acc += mrow[448 + j] * l0b[j];
    g_bias[o] = acc;
}

// ---------------- NMS (separable 9x9 max pools) ----------------
__global__ void k_hmax(const float* __restrict__ sc)
{
    int i = blockIdx.x*blockDim.x + threadIdx.x;
    if (i >= BHW) return;
    int x = i % WW;
    int lo = (x >= RAD) ? -RAD : -x;
    int hi = (x < WW-RAD) ? RAD : (WW-1-x);
    float m = -INFINITY;
    for (int d = lo; d <= hi; d++) m = fmaxf(m, sc[i+d]);
    g_tmpA[i] = m;
}

__global__ void k_vmax_eq(const float* __restrict__ sc)
{
    int i = blockIdx.x*blockDim.x + threadIdx.x;
    if (i >= BHW) return;
    int y = (i / WW) % HH;
    int lo = (y >= RAD) ? -RAD : -y;
    int hi = (y < HH-RAD) ? RAD : (HH-1-y);
    float m = -INFINITY;
    for (int d = lo; d <= hi; d++) m = fmaxf(m, g_tmpA[i + d*WW]);
    g_maxmask[i] = (sc[i] == m) ? 1 : 0;
}

__global__ void k_hor()
{
    int i = blockIdx.x*blockDim.x + threadIdx.x;
    if (i >= BHW) return;
    int x = i % WW;
    int lo = (x >= RAD) ? -RAD : -x;
    int hi = (x < WW-RAD) ? RAD : (WW-1-x);
    unsigned char m = 0;
    for (int d = lo; d <= hi; d++) m |= g_maxmask[i+d];
    g_tmpm[i] = m;
}

__global__ void k_vor()
{
    int i = blockIdx.x*blockDim.x + threadIdx.x;
    if (i >= BHW) return;
    int y = (i / WW) % HH;
    int lo = (y >= RAD) ? -RAD : -y;
    int hi = (y < HH-RAD) ? RAD : (HH-1-y);
    unsigned char m = 0;
    for (int d = lo; d <= hi; d++) m |= g_tmpm[i + d*WW];
    g_supp[i] = m;
}

__global__ void k_hmax_supp(const float* __restrict__ sc)
{
    int i = blockIdx.x*blockDim.x + threadIdx.x;
    if (i >= BHW) return;
    int x = i % WW;
    int lo = (x >= RAD) ? -RAD : -x;
    int hi = (x < WW-RAD) ? RAD : (WW-1-x);
    float m = -INFINITY;
    for (int d = lo; d <= hi; d++) {
        int j = i + d;
        m = fmaxf(m, g_supp[j] ? 0.0f : sc[j]);
    }
    g_tmpA[i] = m;
}

__global__ void k_vmax_combine(const float* __restrict__ sc)
{
    int i = blockIdx.x*blockDim.x + threadIdx.x;
    if (i >= BHW) return;
    int y = (i / WW) % HH;
    int lo = (y >= RAD) ? -RAD : -y;
    int hi = (y < HH-RAD) ? RAD : (HH-1-y);
    float m = -INFINITY;
    for (int d = lo; d <= hi; d++) m = fmaxf(m, g_tmpA[i + d*WW]);
    unsigned char sp = g_supp[i];
    float ss = sp ? 0.0f : sc[i];
    if ((ss == m) && !sp) g_maxmask[i] = 1;
}

// ---------------- candidate compaction + histogram ----------------
__global__ void k_reset()
{
    int i = blockIdx.x*blockDim.x + threadIdx.x;
    if (i < BB) g_count[i] = 0;
    if (i < BB*NBUCK) g_hist[i] = 0;
}

__global__ void k_cand(const float* __restrict__ sc)
{
    int i = blockIdx.x*blockDim.x + threadIdx.x;
    if (i >= BHW) return;
    if (!g_maxmask[i]) return;
    float s = sc[i];
    if (!(s > THR)) return;
    int local = i % HWW;
    int x = local % WW, y = local / WW;
    if (x < RAD || x >= WW-RAD || y < RAD || y >= HH-RAD) return;  // BORDER==4
    int b = i / HWW;
    unsigned sb = __float_as_uint(s);           // positive float: order-preserving
    int p = atomicAdd(&g_count[b], 1);
    if (p < CAP)
        g_cand[b*CAP + p] = (((unsigned long long)sb) << 32)
                          | (unsigned long long)(0xFFFFFFFFu - (unsigned)local);
    atomicAdd(&g_hist[b*NBUCK + (sb >> 20)], 1);
}

// ---------------- two-level radix-select + bitonic sort of survivors ----------------
__global__ void __launch_bounds__(1024) k_select(float* __restrict__ outKp,
                                                 float* __restrict__ outSc)
{
    __shared__ int sv[1024];
    __shared__ int hist2[NBUCK];
    __shared__ unsigned long long sel[SELCAP];
    __shared__ int s_m;
    __shared__ int s_T;
    __shared__ int s_T2;
    __shared__ int s_nhi;
    int b = blockIdx.x;
    int tid = threadIdx.x;
    int cnt = g_count[b]; if (cnt > CAP) cnt = CAP;

    // ---- level 1: coarse bucket (float bits 31..20) ----
    int c0 = g_hist[b*NBUCK + tid*4 + 0];
    int c1 = g_hist[b*NBUCK + tid*4 + 1];
    int c2 = g_hist[b*NBUCK + tid*4 + 2];
    int c3 = g_hist[b*NBUCK + tid*4 + 3];
    sv[tid] = c0 + c1 + c2 + c3;
    if (tid == 0) { s_T = 0; s_T2 = 0; s_m = 0; s_nhi = 0; }
    __syncthreads();
    for (int off = 1; off < 1024; off <<= 1) {              // suffix scan
        int add = (tid + off < 1024) ? sv[tid + off] : 0;
        __syncthreads();
        sv[tid] += add;
        __syncthreads();
    }
    {
        int nextChunk = (tid < 1023) ? sv[tid+1] : 0;
        int C3v = nextChunk + c3;
        int C2v = C3v + c2;
        int C1v = C2v + c1;
        int C0v = C1v + c0;
        if (C0v >= MAXKP && C1v       < MAXKP) s_T = tid*4 + 0;
        if (C1v >= MAXKP && C2v       < MAXKP) s_T = tid*4 + 1;
        if (C2v >= MAXKP && C3v       < MAXKP) s_T = tid*4 + 2;
        if (C3v >= MAXKP && nextChunk < MAXKP) s_T = tid*4 + 3;
    }
    __syncthreads();
    int Tstar = s_T;   // 0 if total < 1024 -> select everything

    // ---- level 2: refine within bucket Tstar on float bits 19..8 ----
    for (int t = tid; t < NBUCK; t += 1024) hist2[t] = 0;
    __syncthreads();
    for (int t = tid; t < cnt; t += 1024) {
        unsigned long long key = g_cand[b*CAP + t];
        int bucket = (int)(key >> 52);
        if (bucket > Tstar)        atomicAdd(&s_nhi, 1);
        else if (bucket == Tstar)  atomicAdd(&hist2[(int)((key >> 40) & 0xFFF)], 1);
    }
    __syncthreads();
    int q0 = hist2[tid*4 + 0];
    int q1 = hist2[tid*4 + 1];
    int q2 = hist2[tid*4 + 2];
    int q3 = hist2[tid*4 + 3];
    sv[tid] = q0 + q1 + q2 + q3;
    int nhi = s_nhi;           // < MAXKP by construction of Tstar
    __syncthreads();
    for (int off = 1; off < 1024; off <<= 1) {
        int add = (tid + off < 1024) ? sv[tid + off] : 0;
        __syncthreads();
        sv[tid] += add;
        __syncthreads();
    }
    {
        int nextChunk = (tid < 1023) ? sv[tid+1] : 0;
        int D3 = nextChunk + q3;
        int D2 = D3 + q2;
        int D1 = D2 + q1;
        int D0 = D1 + q0;
        if (nhi + D0 >= MAXKP && nhi + D1        < MAXKP) s_T2 = tid*4 + 0;
        if (nhi + D1 >= MAXKP && nhi + D2        < MAXKP) s_T2 = tid*4 + 1;
        if (nhi + D2 >= MAXKP && nhi + D3        < MAXKP) s_T2 = tid*4 + 2;
        if (nhi + D3 >= MAXKP && nhi + nextChunk < MAXKP) s_T2 = tid*4 + 3;
    }
    __syncthreads();
    int T2 = s_T2;             // 0 if total < 1024 -> select everything

    // ---- gather survivors (expected ~= 1024 + O(1), bounded by SELCAP) ----
    for (int t = tid; t < cnt; t += 1024) {
        unsigned long long key = g_cand[b*CAP + t];
        int bucket = (int)(key >> 52);
        int sub    = (int)((key >> 40) & 0xFFF);
        if (bucket > Tstar || (bucket == Tstar && sub >= T2)) {
            int p = atomicAdd(&s_m, 1);
            if (p < SELCAP) sel[p] = key;
        }
    }
    __syncthreads();
    int m = s_m; if (m > SELCAP) m = SELCAP;
    for (int t = tid; t < SELCAP; t += 1024) if (t >= m) sel[t] = 0ULL;
    __syncthreads();

    // ---- bitonic sort descending (score desc, idx asc via ~idx) ----
    for (int k = 2; k <= SELCAP; k <<= 1) {
        for (int j = k >> 1; j > 0; j >>= 1) {
            for (int t = tid; t < SELCAP; t += 1024) {
                int l = t ^ j;
                if (l > t) {
                    unsigned long long a = sel[t], c = sel[l];
                    bool descB = ((t & k) == 0);
                    if (descB ? (a < c) : (a > c)) { sel[t] = c; sel[l] = a; }
                }
            }
            __syncthreads();
        }
    }

    // ---- emit top-1024 (pad with -1 scores at idx 0,1,2,...) ----
    for (int t = tid; t < MAXKP; t += 1024) {
        float s; int idx;
        if (t < m) {
            unsigned long long key = sel[t];
            s   = __uint_as_float((unsigned)(key >> 32));
            idx = (int)(0xFFFFFFFFu - (unsigned)(key & 0xFFFFFFFFu));
        } else {
            s = -1.0f; idx = t - m;
        }
        outKp[(b*MAXKP + t)*2 + 0] = (float)(idx % WW);
        outKp[(b*MAXKP + t)*2 + 1] = (float)(idx / WW);
        outSc[b*MAXKP + t] = s;
        g_selidx[b*MAXKP + t] = idx;
    }
}

// ---------------- descriptor sampling (bilinear + L2 norm) ----------------
__device__ __forceinline__ void sample_scale(
    const float* __restrict__ dptr, int C, int h, int w, int sfac,
    float kx, float ky, float* __restrict__ xrow, int off, float* red)
{
    int tid = threadIdx.x;
    float kxs = kx - (float)sfac * 0.5f + 0.5f;
    float kys = ky - (float)sfac * 0.5f + 0.5f;
    float gx = kxs / (float)(w * sfac - 1) * 2.0f - 1.0f;
    float gy = kys / (float)(h * sfac - 1) * 2.0f - 1.0f;
    float x = (gx + 1.0f) * 0.5f * (float)(w - 1);
    float y = (gy + 1.0f) * 0.5f * (float)(h - 1);
    float x0f = floorf(x), y0f = floorf(y);
    float wx1 = x - x0f, wy1 = y - y0f;
    float wx0 = 1.0f - wx1, wy0 = 1.0f - wy1;
    int x0 = (int)x0f, y0 = (int)y0f;
    int x1 = x0 + 1,  y1 = y0 + 1;
    int xc0 = min(max(x0, 0), w-1), xc1 = min(max(x1, 0), w-1);
    int yc0 = min(max(y0, 0), h-1), yc1 = min(max(y1, 0), h-1);
    float f00 = (x0 >= 0 && x0 < w && y0 >= 0 && y0 < h) ? 1.f : 0.f;
    float f10 = (x1 >= 0 && x1 < w && y0 >= 0 && y0 < h) ? 1.f : 0.f;
    float f01 = (x0 >= 0 && x0 < w && y1 >= 0 && y1 < h) ? 1.f : 0.f;
    float f11 = (x1 >= 0 && x1 < w && y1 >= 0 && y1 < h) ? 1.f : 0.f;
    float w00 = (wx0*wy0)*f00, w10 = (wx1*wy0)*f10;
    float w01 = (wx0*wy1)*f01, w11 = (wx1*wy1)*f11;

    float rv = 0.f, sq = 0.f;
    if (tid < C) {
        const float* base = dptr + (size_t)tid * h * w;
        float g00 = __ldg(base + yc0*w + xc0);
        float g10 = __ldg(base + yc0*w + xc1);
        float g01 = __ldg(base + yc1*w + xc0);
        float g11 = __ldg(base + yc1*w + xc1);
        rv = g00*w00 + g10*w10 + g01*w01 + g11*w11;
        sq = rv*rv;
    }
    red[tid] = sq;
    __syncthreads();
    for (int st = 128; st > 0; st >>= 1) {
        if (tid < st) red[tid] += red[tid + st];
        __syncthreads();
    }
    float nrm = fmaxf(sqrtf(red[0]), 1e-12f);
    __syncthreads();   // red reused by next scale
    if (tid < C) xrow[off + tid] = rv / nrm;
}

__global__ void __launch_bounds__(256) k_sample(
    const float* __restrict__ d1, const float* __restrict__ d2,
    const float* __restrict__ d3, const float* __restrict__ d4)
{
    __shared__ float red[256];
    int n = blockIdx.x;
    int b = n / MAXKP;
    int idx = g_selidx[n];
    float kx = (float)(idx % WW), ky = (float)(idx / WW);
    float* xrow = g_X + (size_t)n * KTOT;
    sample_scale(d1 + (size_t)b*C1*H1*W1, C1, H1, W1, 2,  kx, ky, xrow, 0,   red);
    sample_scale(d2 + (size_t)b*C2*H2*W2, C2, H2, W2, 4,  kx, ky, xrow, 64,  red);
    sample_scale(d3 + (size_t)b*C3*H3*W3, C3, H3, W3, 8,  kx, ky, xrow, 192, red);
    sample_scale(d4 + (size_t)b*C4*H4*W4, C4, H4, W4, 16, kx, ky, xrow, 448, red);
}

// ---------------- final GEMM: out[256, 4096] = M[256,704] @ X^T + bias ----------------
#define GBM 64
#define GBN 64
#define GBK 16
#define GPAD 68

__global__ void __launch_bounds__(256) k_gemm(float* __restrict__ outDesc)
{
    __shared__ float sM[GBK][GPAD];
    __shared__ float sX[GBK][GPAD];
    int tid = threadIdx.x;
    int tx = tid & 15, ty = tid >> 4;
    int o0 = blockIdx.y * GBM;
    int n0 = blockIdx.x * GBN;
    float acc[4][4];
    #pragma unroll
    for (int i = 0; i < 4; i++)
        #pragma unroll
        for (int j = 0; j < 4; j++) acc[i][j] = 0.f;

    for (int k0 = 0; k0 < KTOT; k0 += GBK) {
        #pragma unroll
        for (int r = 0; r < 4; r++) {
            int e = tid + r*256;
            int row = e >> 4;     // 0..63
            int kk  = e & 15;
            sM[kk][row] = g_M[(o0 + row)*KTOT + k0 + kk];
            sX[kk][row] = g_X[(size_t)(n0 + row)*KTOT + k0 + kk];
        }
        __syncthreads();
        #pragma unroll
        for (int kk = 0; kk < GBK; kk++) {
            float4 av = *(const float4*)&sM[kk][ty*4];
            float4 bv = *(const float4*)&sX[kk][tx*4];
            float a[4] = {av.x, av.y, av.z, av.w};
            float bb_[4] = {bv.x, bv.y, bv.z, bv.w};
            #pragma unroll
            for (int i = 0; i < 4; i++)
                #pragma unroll
                for (int j = 0; j < 4; j++) acc[i][j] += a[i]*bb_[j];
        }
        __syncthreads();
    }

    int bIdx  = n0 / MAXKP;
    int tBase = (n0 % MAXKP) + tx*4;
    #pragma unroll
    for (int i = 0; i < 4; i++) {
        int o = o0 + ty*4 + i;
        float bias = g_bias[o];
        float4 v = make_float4(acc[i][0]+bias, acc[i][1]+bias,
                               acc[i][2]+bias, acc[i][3]+bias);
        *(float4*)&outDesc[(size_t)(bIdx*256 + o)*MAXKP + tBase] = v;
    }
}

// ---------------- launch ----------------
extern "C" void kernel_launch(void* const* d_in, const int* in_sizes, int n_in,
                              void* d_out, int out_size)
{
    const float* scores  = (const float*)d_in[0];
    const float* d1      = (const float*)d_in[1];
    const float* d2      = (const float*)d_in[2];
    const float* d3      = (const float*)d_in[3];   // cDa
    const float* d4      = (const float*)d_in[4];
    const float* lin0_w  = (const float*)d_in[5];
    const float* lin0_b  = (const float*)d_in[6];
    const float* lin1_w  = (const float*)d_in[7];
    const float* lin1_b  = (const float*)d_in[8];
    const float* lin2_w  = (const float*)d_in[9];
    const float* lin2_b  = (const float*)d_in[10];
    const float* merge_w = (const float*)d_in[11];
    const float* merge_b = (const float*)d_in[12];

    float* out     = (float*)d_out;
    float* outKp   = out;                          // [4,1024,2]
    float* outSc   = out + BB*MAXKP*2;             // [4,1024]
    float* outDesc = out + BB*MAXKP*2 + BB*MAXKP;  // [4,256,1024]

    const int nb = (BHW + 255) / 256;

    // folded weights (independent of NMS chain)
    k_fold<<<(256*KTOT + 255)/256, 256>>>(merge_w, lin0_w, lin1_w, lin2_w);
    k_foldbias<<<1, 256>>>(merge_w, merge_b, lin0_b, lin1_b, lin2_b);

    // simple_nms
    k_hmax<<<nb, 256>>>(scores);
    k_vmax_eq<<<nb, 256>>>(scores);
    for (int it = 0; it < 2; it++) {
        k_hor<<<nb, 256>>>();
        k_vor<<<nb, 256>>>();
        k_hmax_supp<<<nb, 256>>>(scores);
        k_vmax_combine<<<nb, 256>>>(scores);
    }

    // top-k
    k_reset<<<(BB*NBUCK + 255)/256, 256>>>();
    k_cand<<<nb, 256>>>(scores);
    k_select<<<BB, 1024>>>(outKp, outSc);

    // descriptors
    k_sample<<<BB*MAXKP, 256>>>(d1, d2, d3, d4);
    k_gemm<<<dim3((BB*MAXKP)/GBN, 256/GBM), 256>>>(outDesc);
}

// round 3
// speedup vs baseline: 1.1658x; 1.1658x over previous
#include <cuda_runtime.h>
#include <math.h>

// ---------------- problem constants ----------------
#define BB 4
#define HH 480
#define WW 640
#define HWW (HH*WW)          // 307200
#define BHW (BB*HWW)         // 1228800
#define RAD 4
#define THR 0.005f
#define MAXKP 1024
#define CAP 16384
#define NBUCK 4096
#define SELCAP 2048
#define KTOT 704

// feature maps
#define C1 64
#define H1 240
#define W1 320
#define C2 128
#define H2 120
#define W2 160
#define C3 256
#define H3 60
#define W3 80
#define C4 256
#define H4 30
#define W4 40

// NMS tile
#define TX 64
#define TY 16
#define TXH (TX+8)
#define TYH (TY+8)
#define SSTR (TXH+1)   // 73
#define HSTR (TX+1)    // 65

// ---------------- scratch ----------------
__device__ unsigned char      g_maxmask[BHW];
__device__ unsigned char      g_supp[BHW];
__device__ unsigned long long g_cand[BB*CAP];
__device__ int                g_count[BB];
__device__ int                g_hist[BB*NBUCK];
__device__ int                g_selidx[BB*MAXKP];
__device__ __align__(16) float g_X[(size_t)BB*MAXKP*KTOT];
__device__ __align__(16) float g_M[256*KTOT];
__device__ float              g_bias[256];

// ---------------- weight folding ----------------
__global__ void k_fold(const float* __restrict__ mw,
                       const float* __restrict__ l0w, const float* __restrict__ l1w,
                       const float* __restrict__ l2w)
{
    int t = blockIdx.x*blockDim.x + threadIdx.x;
    if (t >= 256*KTOT) return;
    int o = t / KTOT, i = t % KTOT;
    const float* mrow = mw + o*KTOT;
    float acc = 0.f;
    if (i < 64) {
        for (int j = 0; j < 64; j++)  acc += mrow[j]       * l2w[j*64  + i];
    } else if (i < 192) {
        int ii = i - 64;
        for (int j = 0; j < 128; j++) acc += mrow[64 + j]  * l1w[j*128 + ii];
    } else if (i < 448) {
        acc = mrow[i];
    } else {
        int ii = i - 448;
        for (int j = 0; j < 256; j++) acc += mrow[448 + j] * l0w[j*256 + ii];
    }
    g_M[t] = acc;
}

__global__ void k_foldbias(const float* __restrict__ mw, const float* __restrict__ mb,
                           const float* __restrict__ l0b, const float* __restrict__ l1b,
                           const float* __restrict__ l2b)
{
    int o = threadIdx.x;   // 256 threads
    const float* mrow = mw + o*KTOT;
    float acc = mb[o];
    for (int j = 0; j < 64;  j++) acc += mrow[j]       * l2b[j];
    for (int j = 0; j < 128; j++) acc += mrow[64 + j]  * l1b[j];
    for (int j = 0; j < 256; j++) acc += mrow[448 + j] * l0b[j];
    g_bias[o] = acc;
}

// ---------------- fused NMS kernels (tiled separable 9x9 pools) ----------------

// maxmask = (sc == maxpool9(sc))
__global__ void __launch_bounds__(256) k_nms1(const float* __restrict__ sc)
{
    __shared__ float s[TYH][SSTR];
    __shared__ float hm[TYH][HSTR];
    int b = blockIdx.z;
    int x0 = blockIdx.x*TX, y0 = blockIdx.y*TY;
    const float* S = sc + b*HWW;

    for (int e = threadIdx.x; e < TYH*TXH; e += 256) {
        int ly = e / TXH, lx = e % TXH;
        int gx = x0 + lx - 4, gy = y0 + ly - 4;
        float v = -INFINITY;
        if (gx >= 0 && gx < WW && gy >= 0 && gy < HH) v = S[gy*WW + gx];
        s[ly][lx] = v;
    }
    __syncthreads();
    for (int e = threadIdx.x; e < TYH*TX; e += 256) {
        int ly = e / TX, lx = e % TX;
        float m = s[ly][lx];
        #pragma unroll
        for (int d = 1; d < 9; d++) m = fmaxf(m, s[ly][lx+d]);
        hm[ly][lx] = m;
    }
    __syncthreads();
    for (int e = threadIdx.x; e < TY*TX; e += 256) {
        int ly = e / TX, lx = e % TX;
        float m = hm[ly][lx];
        #pragma unroll
        for (int d = 1; d < 9; d++) m = fmaxf(m, hm[ly+d][lx]);
        int gx = x0 + lx, gy = y0 + ly;
        g_maxmask[b*HWW + gy*WW + gx] = (s[ly+4][lx+4] == m) ? 1 : 0;
    }
}

// supp = dilate9(maxmask)
__global__ void __launch_bounds__(256) k_nms2()
{
    __shared__ unsigned char s[TYH][SSTR];
    __shared__ unsigned char hm[TYH][HSTR];
    int b = blockIdx.z;
    int x0 = blockIdx.x*TX, y0 = blockIdx.y*TY;
    const unsigned char* S = g_maxmask + b*HWW;

    for (int e = threadIdx.x; e < TYH*TXH; e += 256) {
        int ly = e / TXH, lx = e % TXH;
        int gx = x0 + lx - 4, gy = y0 + ly - 4;
        unsigned char v = 0;
        if (gx >= 0 && gx < WW && gy >= 0 && gy < HH) v = S[gy*WW + gx];
        s[ly][lx] = v;
    }
    __syncthreads();
    for (int e = threadIdx.x; e < TYH*TX; e += 256) {
        int ly = e / TX, lx = e % TX;
        unsigned char m = s[ly][lx];
        #pragma unroll
        for (int d = 1; d < 9; d++) m |= s[ly][lx+d];
        hm[ly][lx] = m;
    }
    __syncthreads();
    for (int e = threadIdx.x; e < TY*TX; e += 256) {
        int ly = e / TX, lx = e % TX;
        unsigned char m = hm[ly][lx];
        #pragma unroll
        for (int d = 1; d < 9; d++) m |= hm[ly+d][lx];
        int gx = x0 + lx, gy = y0 + ly;
        g_supp[b*HWW + gy*WW + gx] = m;
    }
}

// ss = supp?0:sc;  mask |= (ss == maxpool9(ss)) & !supp
// EMIT: additionally run threshold/border test and emit candidates (final pass)
template<int EMIT>
__global__ void __launch_bounds__(256) k_nms3(const float* __restrict__ sc)
{
    __shared__ float s[TYH][SSTR];
    __shared__ float hm[TYH][HSTR];
    int b = blockIdx.z;
    int x0 = blockIdx.x*TX, y0 = blockIdx.y*TY;
    const float* S = sc + b*HWW;
    const unsigned char* SP = g_supp + b*HWW;

    for (int e = threadIdx.x; e < TYH*TXH; e += 256) {
        int ly = e / TXH, lx = e % TXH;
        int gx = x0 + lx - 4, gy = y0 + ly - 4;
        float v = -INFINITY;
        if (gx >= 0 && gx < WW && gy >= 0 && gy < HH) {
            int gi = gy*WW + gx;
            v = SP[gi] ? 0.0f : S[gi];
        }
        s[ly][lx] = v;
    }
    __syncthreads();
    for (int e = threadIdx.x; e < TYH*TX; e += 256) {
        int ly = e / TX, lx = e % TX;
        float m = s[ly][lx];
        #pragma unroll
        for (int d = 1; d < 9; d++) m = fmaxf(m, s[ly][lx+d]);
        hm[ly][lx] = m;
    }
    __syncthreads();
    for (int e = threadIdx.x; e < TY*TX; e += 256) {
        int ly = e / TX, lx = e % TX;
        float m = hm[ly][lx];
        #pragma unroll
        for (int d = 1; d < 9; d++) m = fmaxf(m, hm[ly+d][lx]);
        int gx = x0 + lx, gy = y0 + ly;
        int gi = b*HWW + gy*WW + gx;
        unsigned char sp = g_supp[gi];
        float ss = s[ly+4][lx+4];                 // already supp-zeroed
        unsigned char newm = ((ss == m) && !sp) ? 1 : 0;
        unsigned char maskv = g_maxmask[gi] | newm;
        if (EMIT) {
            // final mask: candidate test (scores>THR, inside border)
            if (maskv && gx >= RAD && gx < WW-RAD && gy >= RAD && gy < HH-RAD) {
                float sv = S[gy*WW + gx];
                if (sv > THR) {
                    unsigned sb = __float_as_uint(sv);
                    int local = gy*WW + gx;
                    int p = atomicAdd(&g_count[b], 1);
                    if (p < CAP)
                        g_cand[b*CAP + p] = (((unsigned long long)sb) << 32)
                                          | (unsigned long long)(0xFFFFFFFFu - (unsigned)local);
                    atomicAdd(&g_hist[b*NBUCK + (sb >> 20)], 1);
                }
            }
        } else {
            g_maxmask[gi] = maskv;
        }
    }
}

// ---------------- reset ----------------
__global__ void k_reset()
{
    int i = blockIdx.x*blockDim.x + threadIdx.x;
    if (i < BB) g_count[i] = 0;
    if (i < BB*NBUCK) g_hist[i] = 0;
}

// ---------------- two-level radix-select + bitonic sort ----------------
__global__ void __launch_bounds__(1024) k_select(float* __restrict__ outKp,
                                                 float* __restrict__ outSc)
{
    __shared__ int sv[1024];
    __shared__ int hist2[NBUCK];
    __shared__ unsigned long long sel[SELCAP];
    __shared__ int s_m;
    __shared__ int s_T;
    __shared__ int s_T2;
    __shared__ int s_nhi;
    int b = blockIdx.x;
    int tid = threadIdx.x;
    int cnt = g_count[b]; if (cnt > CAP) cnt = CAP;

    // level 1: coarse bucket (float bits 31..20)
    int c0 = g_hist[b*NBUCK + tid*4 + 0];
    int c1 = g_hist[b*NBUCK + tid*4 + 1];
    int c2 = g_hist[b*NBUCK + tid*4 + 2];
    int c3 = g_hist[b*NBUCK + tid*4 + 3];
    sv[tid] = c0 + c1 + c2 + c3;
    if (tid == 0) { s_T = 0; s_T2 = 0; s_m = 0; s_nhi = 0; }
    __syncthreads();
    for (int off = 1; off < 1024; off <<= 1) {
        int add = (tid + off < 1024) ? sv[tid + off] : 0;
        __syncthreads();
        sv[tid] += add;
        __syncthreads();
    }
    {
        int nextChunk = (tid < 1023) ? sv[tid+1] : 0;
        int C3v = nextChunk + c3;
        int C2v = C3v + c2;
        int C1v = C2v + c1;
        int C0v = C1v + c0;
        if (C0v >= MAXKP && C1v       < MAXKP) s_T = tid*4 + 0;
        if (C1v >= MAXKP && C2v       < MAXKP) s_T = tid*4 + 1;
        if (C2v >= MAXKP && C3v       < MAXKP) s_T = tid*4 + 2;
        if (C3v >= MAXKP && nextChunk < MAXKP) s_T = tid*4 + 3;
    }
    __syncthreads();
    int Tstar = s_T;

    // level 2: refine on float bits 19..8 within bucket Tstar
    for (int t = tid; t < NBUCK; t += 1024) hist2[t] = 0;
    __syncthreads();
    for (int t = tid; t < cnt; t += 1024) {
        unsigned long long key = g_cand[b*CAP + t];
        int bucket = (int)(key >> 52);
        if (bucket > Tstar)        atomicAdd(&s_nhi, 1);
        else if (bucket == Tstar)  atomicAdd(&hist2[(int)((key >> 40) & 0xFFF)], 1);
    }
    __syncthreads();
    int q0 = hist2[tid*4 + 0];
    int q1 = hist2[tid*4 + 1];
    int q2 = hist2[tid*4 + 2];
    int q3 = hist2[tid*4 + 3];
    sv[tid] = q0 + q1 + q2 + q3;
    int nhi = s_nhi;
    __syncthreads();
    for (int off = 1; off < 1024; off <<= 1) {
        int add = (tid + off < 1024) ? sv[tid + off] : 0;
        __syncthreads();
        sv[tid] += add;
        __syncthreads();
    }
    {
        int nextChunk = (tid < 1023) ? sv[tid+1] : 0;
        int D3 = nextChunk + q3;
        int D2 = D3 + q2;
        int D1 = D2 + q1;
        int D0 = D1 + q0;
        if (nhi + D0 >= MAXKP && nhi + D1        < MAXKP) s_T2 = tid*4 + 0;
        if (nhi + D1 >= MAXKP && nhi + D2        < MAXKP) s_T2 = tid*4 + 1;
        if (nhi + D2 >= MAXKP && nhi + D3        < MAXKP) s_T2 = tid*4 + 2;
        if (nhi + D3 >= MAXKP && nhi + nextChunk < MAXKP) s_T2 = tid*4 + 3;
    }
    __syncthreads();
    int T2 = s_T2;

    // gather survivors
    for (int t = tid; t < cnt; t += 1024) {
        unsigned long long key = g_cand[b*CAP + t];
        int bucket = (int)(key >> 52);
        int sub    = (int)((key >> 40) & 0xFFF);
        if (bucket > Tstar || (bucket == Tstar && sub >= T2)) {
            int p = atomicAdd(&s_m, 1);
            if (p < SELCAP) sel[p] = key;
        }
    }
    __syncthreads();
    int m = s_m; if (m > SELCAP) m = SELCAP;
    for (int t = tid; t < SELCAP; t += 1024) if (t >= m) sel[t] = 0ULL;
    __syncthreads();

    // bitonic sort descending
    for (int k = 2; k <= SELCAP; k <<= 1) {
        for (int j = k >> 1; j > 0; j >>= 1) {
            for (int t = tid; t < SELCAP; t += 1024) {
                int l = t ^ j;
                if (l > t) {
                    unsigned long long a = sel[t], c = sel[l];
                    bool descB = ((t & k) == 0);
                    if (descB ? (a < c) : (a > c)) { sel[t] = c; sel[l] = a; }
                }
            }
            __syncthreads();
        }
    }

    // emit top-1024
    for (int t = tid; t < MAXKP; t += 1024) {
        float s; int idx;
        if (t < m) {
            unsigned long long key = sel[t];
            s   = __uint_as_float((unsigned)(key >> 32));
            idx = (int)(0xFFFFFFFFu - (unsigned)(key & 0xFFFFFFFFu));
        } else {
            s = -1.0f; idx = t - m;
        }
        outKp[(b*MAXKP + t)*2 + 0] = (float)(idx % WW);
        outKp[(b*MAXKP + t)*2 + 1] = (float)(idx / WW);
        outSc[b*MAXKP + t] = s;
        g_selidx[b*MAXKP + t] = idx;
    }
}

// ---------------- one-pass descriptor sampling (704 thr: thread == channel) ----------------
__global__ void __launch_bounds__(704) k_sample(
    const float* __restrict__ d1, const float* __restrict__ d2,
    const float* __restrict__ d3, const float* __restrict__ d4)
{
    __shared__ float wsum[22];
    int n = blockIdx.x;
    int b = n >> 10;
    int tid = threadIdx.x;
    int idx = g_selidx[n];
    float kx = (float)(idx % WW), ky = (float)(idx / WW);

    const float* dptr; int C, h, w, sfac, ch, warp0, nw;
    if (tid < 64)       { dptr = d1 + (size_t)b*C1*H1*W1; C=C1; h=H1; w=W1; sfac=2;  ch=tid;     warp0=0;  nw=2; }
    else if (tid < 192) { dptr = d2 + (size_t)b*C2*H2*W2; C=C2; h=H2; w=W2; sfac=4;  ch=tid-64;  warp0=2;  nw=4; }
    else if (tid < 448) { dptr = d3 + (size_t)b*C3*H3*W3; C=C3; h=H3; w=W3; sfac=8;  ch=tid-192; warp0=6;  nw=8; }
    else                { dptr = d4 + (size_t)b*C4*H4*W4; C=C4; h=H4; w=W4; sfac=16; ch=tid-448; warp0=14; nw=8; }

    float kxs = kx - (float)sfac * 0.5f + 0.5f;
    float kys = ky - (float)sfac * 0.5f + 0.5f;
    float gx = kxs / (float)(w * sfac - 1) * 2.0f - 1.0f;
    float gy = kys / (float)(h * sfac - 1) * 2.0f - 1.0f;
    float x = (gx + 1.0f) * 0.5f * (float)(w - 1);
    float y = (gy + 1.0f) * 0.5f * (float)(h - 1);
    float x0f = floorf(x), y0f = floorf(y);
    float wx1 = x - x0f, wy1 = y - y0f;
    float wx0 = 1.0f - wx1, wy0 = 1.0f - wy1;
    int x0 = (int)x0f, y0 = (int)y0f;
    int x1 = x0 + 1,  y1 = y0 + 1;
    int xc0 = min(max(x0, 0), w-1), xc1 = min(max(x1, 0), w-1);
    int yc0 = min(max(y0, 0), h-1), yc1 = min(max(y1, 0), h-1);
    float f00 = (x0 >= 0 && x0 < w && y0 >= 0 && y0 < h) ? 1.f : 0.f;
    float f10 = (x1 >= 0 && x1 < w && y0 >= 0 && y0 < h) ? 1.f : 0.f;
    float f01 = (x0 >= 0 && x0 < w && y1 >= 0 && y1 < h) ? 1.f : 0.f;
    float f11 = (x1 >= 0 && x1 < w && y1 >= 0 && y1 < h) ? 1.f : 0.f;
    float w00 = (wx0*wy0)*f00, w10 = (wx1*wy0)*f10;
    float w01 = (wx0*wy1)*f01, w11 = (wx1*wy1)*f11;

    const float* base = dptr + (size_t)ch * h * w;
    float g00 = __ldg(base + yc0*w + xc0);
    float g10 = __ldg(base + yc0*w + xc1);
    float g01 = __ldg(base + yc1*w + xc0);
    float g11 = __ldg(base + yc1*w + xc1);
    float rv = g00*w00 + g10*w10 + g01*w01 + g11*w11;
    float sq = rv*rv;

    // warp reduce (each warp entirely within one group)
    #pragma unroll
    for (int o = 16; o > 0; o >>= 1) sq += __shfl_xor_sync(0xFFFFFFFFu, sq, o);
    int wid = tid >> 5;
    if ((tid & 31) == 0) wsum[wid] = sq;
    __syncthreads();
    float tot = 0.f;
    for (int i = 0; i < nw; i++) tot += wsum[warp0 + i];
    float nrm = fmaxf(sqrtf(tot), 1e-12f);
    g_X[(size_t)n * KTOT + tid] = rv / nrm;
}

// ---------------- final GEMM: out[256,4096] = M[256,704] @ X^T + bias ----------------
#define GBM 64
#define GBN 64
#define GBK 32
#define GPAD 68

__global__ void __launch_bounds__(256) k_gemm(float* __restrict__ outDesc)
{
    __shared__ float sM[GBK][GPAD];
    __shared__ float sX[GBK][GPAD];
    int tid = threadIdx.x;
    int tx = tid & 15, ty = tid >> 4;
    int o0 = blockIdx.y * GBM;
    int n0 = blockIdx.x * GBN;
    float acc[4][4];
    #pragma unroll
    for (int i = 0; i < 4; i++)
        #pragma unroll
        for (int j = 0; j < 4; j++) acc[i][j] = 0.f;

    for (int k0 = 0; k0 < KTOT; k0 += GBK) {
        // fill: each array is 64 rows x 32 k = 512 float4 slots; 256 threads x 2
        #pragma unroll
        for (int r = 0; r < 2; r++) {
            int f = tid + r*256;           // 0..511
            int row = f >> 3;              // 0..63
            int kq  = (f & 7) * 4;         // 0,4,...,28
            float4 v = *(const float4*)&g_M[(o0 + row)*KTOT + k0 + kq];
            sM[kq+0][row] = v.x; sM[kq+1][row] = v.y;
            sM[kq+2][row] = v.z; sM[kq+3][row] = v.w;
            float4 u = *(const float4*)&g_X[(size_t)(n0 + row)*KTOT + k0 + kq];
            sX[kq+0][row] = u.x; sX[kq+1][row] = u.y;
            sX[kq+2][row] = u.z; sX[kq+3][row] = u.w;
        }
        __syncthreads();
        #pragma unroll
        for (int kk = 0; kk < GBK; kk++) {
            float4 av = *(const float4*)&sM[kk][ty*4];
            float4 bv = *(const float4*)&sX[kk][tx*4];
            float a[4] = {av.x, av.y, av.z, av.w};
            float bb_[4] = {bv.x, bv.y, bv.z, bv.w};
            #pragma unroll
            for (int i = 0; i < 4; i++)
                #pragma unroll
                for (int j = 0; j < 4; j++) acc[i][j] += a[i]*bb_[j];
        }
        __syncthreads();
    }

    int bIdx  = n0 / MAXKP;
    int tBase = (n0 % MAXKP) + tx*4;
    #pragma unroll
    for (int i = 0; i < 4; i++) {
        int o = o0 + ty*4 + i;
        float bias = g_bias[o];
        float4 v = make_float4(acc[i][0]+bias, acc[i][1]+bias,
                               acc[i][2]+bias, acc[i][3]+bias);
        *(float4*)&outDesc[(size_t)(bIdx*256 + o)*MAXKP + tBase] = v;
    }
}

// ---------------- launch ----------------
extern "C" void kernel_launch(void* const* d_in, const int* in_sizes, int n_in,
                              void* d_out, int out_size)
{
    const float* scores  = (const float*)d_in[0];
    const float* d1      = (const float*)d_in[1];
    const float* d2      = (const float*)d_in[2];
    const float* d3      = (const float*)d_in[3];   // cDa
    const float* d4      = (const float*)d_in[4];
    const float* lin0_w  = (const float*)d_in[5];
    const float* lin0_b  = (const float*)d_in[6];
    const float* lin1_w  = (const float*)d_in[7];
    const float* lin1_b  = (const float*)d_in[8];
    const float* lin2_w  = (const float*)d_in[9];
    const float* lin2_b  = (const float*)d_in[10];
    const float* merge_w = (const float*)d_in[11];
    const float* merge_b = (const float*)d_in[12];

    float* out     = (float*)d_out;
    float* outKp   = out;                          // [4,1024,2]
    float* outSc   = out + BB*MAXKP*2;             // [4,1024]
    float* outDesc = out + BB*MAXKP*2 + BB*MAXKP;  // [4,256,1024]

    dim3 tgrid(WW/TX, HH/TY, BB);   // 10 x 30 x 4

    k_reset<<<(BB*NBUCK + 255)/256, 256>>>();
    k_fold<<<(256*KTOT + 255)/256, 256>>>(merge_w, lin0_w, lin1_w, lin2_w);
    k_foldbias<<<1, 256>>>(merge_w, merge_b, lin0_b, lin1_b, lin2_b);

    // simple_nms: 4 fused passes
    k_nms1<<<tgrid, 256>>>(scores);
    k_nms2<<<tgrid, 256>>>();
    k_nms3<0><<<tgrid, 256>>>(scores);
    k_nms2<<<tgrid, 256>>>();
    k_nms3<1><<<tgrid, 256>>>(scores);   // final: emits candidates + histogram

    // top-k
    k_select<<<BB, 1024>>>(outKp, outSc);

    // descriptors
    k_sample<<<BB*MAXKP, 704>>>(d1, d2, d3, d4);
    k_gemm<<<dim3((BB*MAXKP)/GBN, 256/GBM), 256>>>(outDesc);
}

// round 5
// speedup vs baseline: 1.2753x; 1.0938x over previous
#include <cuda_runtime.h>
#include <cuda_bf16.h>
#include <cstdint>
#include <math.h>

// ---------------- problem constants ----------------
#define BB 4
#define HH 480
#define WW 640
#define HWW (HH*WW)
#define BHW (BB*HWW)
#define RAD 4
#define THR 0.005f
#define MAXKP 1024
#define CAP 16384
#define NBUCK 4096
#define SELCAP 2048
#define KTOT 704

#define C1 64
#define H1 240
#define W1 320
#define C2 128
#define H2 120
#define W2 160
#define C3 256
#define H3 60
#define W3 80
#define C4 256
#define H4 30
#define W4 40

// NMS tiles
#define TX 64
#define TY 16

// ---------------- scratch ----------------
__device__ unsigned char      g_maxmask[BHW];
__device__ unsigned long long g_cand[BB*CAP];
__device__ int                g_count[BB];
__device__ int                g_hist[BB*NBUCK];
__device__ int                g_selidx[BB*MAXKP];
__device__ __align__(16) __nv_bfloat16 g_Xh[(size_t)BB*MAXKP*KTOT];
__device__ __align__(16) __nv_bfloat16 g_Xl[(size_t)BB*MAXKP*KTOT];
__device__ __align__(16) __nv_bfloat16 g_Mh[256*KTOT];
__device__ __align__(16) __nv_bfloat16 g_Ml[256*KTOT];
__device__ float              g_bias[256];

// ---------------- weight folding (+ bf16 hi/lo split) ----------------
__global__ void k_fold(const float* __restrict__ mw,
                       const float* __restrict__ l0w, const float* __restrict__ l1w,
                       const float* __restrict__ l2w)
{
    int t = blockIdx.x*blockDim.x + threadIdx.x;
    if (t >= 256*KTOT) return;
    int o = t / KTOT, i = t % KTOT;
    const float* mrow = mw + o*KTOT;
    float acc = 0.f;
    if (i < 64) {
        for (int j = 0; j < 64; j++)  acc += mrow[j]       * l2w[j*64  + i];
    } else if (i < 192) {
        int ii = i - 64;
        for (int j = 0; j < 128; j++) acc += mrow[64 + j]  * l1w[j*128 + ii];
    } else if (i < 448) {
        acc = mrow[i];
    } else {
        int ii = i - 448;
        for (int j = 0; j < 256; j++) acc += mrow[448 + j] * l0w[j*256 + ii];
    }
    __nv_bfloat16 hi = __float2bfloat16(acc);
    g_Mh[t] = hi;
    g_Ml[t] = __float2bfloat16(acc - __bfloat162float(hi));
}

__global__ void k_foldbias(const float* __restrict__ mw, const float* __restrict__ mb,
                           const float* __restrict__ l0b, const float* __restrict__ l1b,
                           const float* __restrict__ l2b)
{
    int o = threadIdx.x;   // 256 threads
    const float* mrow = mw + o*KTOT;
    float acc = mb[o];
    for (int j = 0; j < 64;  j++) acc += mrow[j]       * l2b[j];
    for (int j = 0; j < 128; j++) acc += mrow[64 + j]  * l1b[j];
    for (int j = 0; j < 256; j++) acc += mrow[448 + j] * l0b[j];
    g_bias[o] = acc;
}

// ---------------- NMS pass 1: maxmask = (sc == maxpool9(sc)) ----------------
__global__ void __launch_bounds__(256) k_nms1(const float* __restrict__ sc)
{
    __shared__ float s[TY+8][TX+8+1];
    __shared__ float hm[TY+8][TX+1];
    int b = blockIdx.z;
    int x0 = blockIdx.x*TX, y0 = blockIdx.y*TY;
    const float* S = sc + b*HWW;

    for (int e = threadIdx.x; e < (TY+8)*(TX+8); e += 256) {
        int ly = e / (TX+8), lx = e % (TX+8);
        int gx = x0 + lx - 4, gy = y0 + ly - 4;
        float v = -INFINITY;
        if (gx >= 0 && gx < WW && gy >= 0 && gy < HH) v = S[gy*WW + gx];
        s[ly][lx] = v;
    }
    __syncthreads();
    for (int e = threadIdx.x; e < (TY+8)*TX; e += 256) {
        int ly = e / TX, lx = e % TX;
        float m = s[ly][lx];
        #pragma unroll
        for (int d = 1; d < 9; d++) m = fmaxf(m, s[ly][lx+d]);
        hm[ly][lx] = m;
    }
    __syncthreads();
    for (int e = threadIdx.x; e < TY*TX; e += 256) {
        int ly = e / TX, lx = e % TX;
        float m = hm[ly][lx];
        #pragma unroll
        for (int d = 1; d < 9; d++) m = fmaxf(m, hm[ly+d][lx]);
        int gx = x0 + lx, gy = y0 + ly;
        g_maxmask[b*HWW + gy*WW + gx] = (s[ly+4][lx+4] == m) ? 1 : 0;
    }
}

// ---------------- fused NMS: supp=dilate9(mask); mask|=(nms of suppressed) ----------------
template<int EMIT>
__global__ void __launch_bounds__(256) k_nms23(const float* __restrict__ sc)
{
    __shared__ unsigned char mm[TY+16][TX+16+4];   // halo 8
    __shared__ unsigned char hor[TY+16][TX+8+4];
    __shared__ unsigned char sup[TY+8][TX+8+4];
    __shared__ float         sfl[TY+8][TX+8+4];
    __shared__ float         hmx[TY+8][TX+4];
    int b = blockIdx.z;
    int x0 = blockIdx.x*TX, y0 = blockIdx.y*TY;
    const float* S = sc + b*HWW;
    const unsigned char* SM = g_maxmask + b*HWW;

    for (int e = threadIdx.x; e < (TY+16)*(TX+16); e += 256) {
        int ly = e / (TX+16), lx = e % (TX+16);
        int gx = x0 + lx - 8, gy = y0 + ly - 8;
        unsigned char v = 0;
        if (gx >= 0 && gx < WW && gy >= 0 && gy < HH) v = SM[gy*WW + gx];
        mm[ly][lx] = v;
    }
    __syncthreads();
    for (int e = threadIdx.x; e < (TY+16)*(TX+8); e += 256) {
        int ly = e / (TX+8), lx = e % (TX+8);
        unsigned char u = mm[ly][lx];
        #pragma unroll
        for (int d = 1; d < 9; d++) u |= mm[ly][lx+d];
        hor[ly][lx] = u;
    }
    __syncthreads();
    for (int e = threadIdx.x; e < (TY+8)*(TX+8); e += 256) {
        int ly = e / (TX+8), lx = e % (TX+8);
        unsigned char u = hor[ly][lx];
        #pragma unroll
        for (int d = 1; d < 9; d++) u |= hor[ly+d][lx];
        sup[ly][lx] = u;
        int gx = x0 + lx - 4, gy = y0 + ly - 4;
        float v = -INFINITY;
        if (gx >= 0 && gx < WW && gy >= 0 && gy < HH) v = u ? 0.0f : S[gy*WW + gx];
        sfl[ly][lx] = v;
    }
    __syncthreads();
    for (int e = threadIdx.x; e < (TY+8)*TX; e += 256) {
        int ly = e / TX, lx = e % TX;
        float m = sfl[ly][lx];
        #pragma unroll
        for (int d = 1; d < 9; d++) m = fmaxf(m, sfl[ly][lx+d]);
        hmx[ly][lx] = m;
    }
    __syncthreads();
    for (int e = threadIdx.x; e < TY*TX; e += 256) {
        int ly = e / TX, lx = e % TX;
        float m = hmx[ly][lx];
        #pragma unroll
        for (int d = 1; d < 9; d++) m = fmaxf(m, hmx[ly+d][lx]);
        unsigned char sp = sup[ly+4][lx+4];
        float ss = sfl[ly+4][lx+4];
        unsigned char newm = ((ss == m) && !sp) ? 1 : 0;
        int gx = x0 + lx, gy = y0 + ly;
        int gi = b*HWW + gy*WW + gx;
        unsigned char maskv = mm[ly+8][lx+8] | newm;
        if (EMIT) {
            if (maskv && gx >= RAD && gx < WW-RAD && gy >= RAD && gy < HH-RAD) {
                float sv = S[gy*WW + gx];
                if (sv > THR) {
                    unsigned sb = __float_as_uint(sv);
                    int local = gy*WW + gx;
                    int p = atomicAdd(&g_count[b], 1);
                    if (p < CAP)
                        g_cand[b*CAP + p] = (((unsigned long long)sb) << 32)
                                          | (unsigned long long)(0xFFFFFFFFu - (unsigned)local);
                    atomicAdd(&g_hist[b*NBUCK + (sb >> 20)], 1);
                }
            }
        } else {
            g_maxmask[gi] = maskv;
        }
    }
}

// ---------------- reset ----------------
__global__ void k_reset()
{
    int i = blockIdx.x*blockDim.x + threadIdx.x;
    if (i < BB) g_count[i] = 0;
    if (i < BB*NBUCK) g_hist[i] = 0;
}

// ---------------- two-level radix-select + bitonic sort ----------------
__global__ void __launch_bounds__(1024) k_select(float* __restrict__ outKp,
                                                 float* __restrict__ outSc)
{
    __shared__ int sv[1024];
    __shared__ int hist2[NBUCK];
    __shared__ unsigned long long sel[SELCAP];
    __shared__ int s_m, s_T, s_T2, s_nhi;
    int b = blockIdx.x;
    int tid = threadIdx.x;
    int cnt = g_count[b]; if (cnt > CAP) cnt = CAP;

    int c0 = g_hist[b*NBUCK + tid*4 + 0];
    int c1 = g_hist[b*NBUCK + tid*4 + 1];
    int c2 = g_hist[b*NBUCK + tid*4 + 2];
    int c3 = g_hist[b*NBUCK + tid*4 + 3];
    sv[tid] = c0 + c1 + c2 + c3;
    if (tid == 0) { s_T = 0; s_T2 = 0; s_m = 0; s_nhi = 0; }
    __syncthreads();
    for (int off = 1; off < 1024; off <<= 1) {
        int add = (tid + off < 1024) ? sv[tid + off] : 0;
        __syncthreads();
        sv[tid] += add;
        __syncthreads();
    }
    {
        int nx = (tid < 1023) ? sv[tid+1] : 0;
        int C3v = nx + c3, C2v = C3v + c2, C1v = C2v + c1, C0v = C1v + c0;
        if (C0v >= MAXKP && C1v < MAXKP) s_T = tid*4 + 0;
        if (C1v >= MAXKP && C2v < MAXKP) s_T = tid*4 + 1;
        if (C2v >= MAXKP && C3v < MAXKP) s_T = tid*4 + 2;
        if (C3v >= MAXKP && nx  < MAXKP) s_T = tid*4 + 3;
    }
    __syncthreads();
    int Tstar = s_T;

    for (int t = tid; t < NBUCK; t += 1024) hist2[t] = 0;
    __syncthreads();
    for (int t = tid; t < cnt; t += 1024) {
        unsigned long long key = g_cand[b*CAP + t];
        int bucket = (int)(key >> 52);
        if (bucket > Tstar)        atomicAdd(&s_nhi, 1);
        else if (bucket == Tstar)  atomicAdd(&hist2[(int)((key >> 40) & 0xFFF)], 1);
    }
    __syncthreads();
    int q0 = hist2[tid*4 + 0], q1 = hist2[tid*4 + 1];
    int q2 = hist2[tid*4 + 2], q3 = hist2[tid*4 + 3];
    sv[tid] = q0 + q1 + q2 + q3;
    int nhi = s_nhi;
    __syncthreads();
    for (int off = 1; off < 1024; off <<= 1) {
        int add = (tid + off < 1024) ? sv[tid + off] : 0;
        __syncthreads();
        sv[tid] += add;
        __syncthreads();
    }
    {
        int nx = (tid < 1023) ? sv[tid+1] : 0;
        int D3 = nx + q3, D2 = D3 + q2, D1 = D2 + q1, D0 = D1 + q0;
        if (nhi + D0 >= MAXKP && nhi + D1 < MAXKP) s_T2 = tid*4 + 0;
        if (nhi + D1 >= MAXKP && nhi + D2 < MAXKP) s_T2 = tid*4 + 1;
        if (nhi + D2 >= MAXKP && nhi + D3 < MAXKP) s_T2 = tid*4 + 2;
        if (nhi + D3 >= MAXKP && nhi + nx < MAXKP) s_T2 = tid*4 + 3;
    }
    __syncthreads();
    int T2 = s_T2;

    for (int t = tid; t < cnt; t += 1024) {
        unsigned long long key = g_cand[b*CAP + t];
        int bucket = (int)(key >> 52);
        int sub    = (int)((key >> 40) & 0xFFF);
        if (bucket > Tstar || (bucket == Tstar && sub >= T2)) {
            int p = atomicAdd(&s_m, 1);
            if (p < SELCAP) sel[p] = key;
        }
    }
    __syncthreads();
    int m = s_m; if (m > SELCAP) m = SELCAP;
    for (int t = tid; t < SELCAP; t += 1024) if (t >= m) sel[t] = 0ULL;
    __syncthreads();

    for (int k = 2; k <= SELCAP; k <<= 1) {
        for (int j = k >> 1; j > 0; j >>= 1) {
            for (int t = tid; t < SELCAP; t += 1024) {
                int l = t ^ j;
                if (l > t) {
                    unsigned long long a = sel[t], c = sel[l];
                    bool descB = ((t & k) == 0);
                    if (descB ? (a < c) : (a > c)) { sel[t] = c; sel[l] = a; }
                }
            }
            __syncthreads();
        }
    }

    for (int t = tid; t < MAXKP; t += 1024) {
        float s; int idx;
        if (t < m) {
            unsigned long long key = sel[t];
            s   = __uint_as_float((unsigned)(key >> 32));
            idx = (int)(0xFFFFFFFFu - (unsigned)(key & 0xFFFFFFFFu));
        } else {
            s = -1.0f; idx = t - m;
        }
        outKp[(b*MAXKP + t)*2 + 0] = (float)(idx % WW);
        outKp[(b*MAXKP + t)*2 + 1] = (float)(idx / WW);
        outSc[b*MAXKP + t] = s;
        g_selidx[b*MAXKP + t] = idx;
    }
}

// ---------------- one-pass descriptor sampling ----------------
__global__ void __launch_bounds__(704) k_sample(
    const float* __restrict__ d1, const float* __restrict__ d2,
    const float* __restrict__ d3, const float* __restrict__ d4)
{
    __shared__ float wsum[22];
    int n = blockIdx.x;
    int b = n >> 10;
    int tid = threadIdx.x;
    int idx = g_selidx[n];
    float kx = (float)(idx % WW), ky = (float)(idx / WW);

    const float* dptr; int h, w, sfac, ch, warp0, nw;
    if (tid < 64)       { dptr = d1 + (size_t)b*C1*H1*W1; h=H1; w=W1; sfac=2;  ch=tid;     warp0=0;  nw=2; }
    else if (tid < 192) { dptr = d2 + (size_t)b*C2*H2*W2; h=H2; w=W2; sfac=4;  ch=tid-64;  warp0=2;  nw=4; }
    else if (tid < 448) { dptr = d3 + (size_t)b*C3*H3*W3; h=H3; w=W3; sfac=8;  ch=tid-192; warp0=6;  nw=8; }
    else                { dptr = d4 + (size_t)b*C4*H4*W4; h=H4; w=W4; sfac=16; ch=tid-448; warp0=14; nw=8; }

    float kxs = kx - (float)sfac * 0.5f + 0.5f;
    float kys = ky - (float)sfac * 0.5f + 0.5f;
    float gx = kxs / (float)(w * sfac - 1) * 2.0f - 1.0f;
    float gy = kys / (float)(h * sfac - 1) * 2.0f - 1.0f;
    float x = (gx + 1.0f) * 0.5f * (float)(w - 1);
    float y = (gy + 1.0f) * 0.5f * (float)(h - 1);
    float x0f = floorf(x), y0f = floorf(y);
    float wx1 = x - x0f, wy1 = y - y0f;
    float wx0 = 1.0f - wx1, wy0 = 1.0f - wy1;
    int x0 = (int)x0f, y0 = (int)y0f;
    int x1 = x0 + 1,  y1 = y0 + 1;
    int xc0 = min(max(x0, 0), w-1), xc1 = min(max(x1, 0), w-1);
    int yc0 = min(max(y0, 0), h-1), yc1 = min(max(y1, 0), h-1);
    float f00 = (x0 >= 0 && x0 < w && y0 >= 0 && y0 < h) ? 1.f : 0.f;
    float f10 = (x1 >= 0 && x1 < w && y0 >= 0 && y0 < h) ? 1.f : 0.f;
    float f01 = (x0 >= 0 && x0 < w && y1 >= 0 && y1 < h) ? 1.f : 0.f;
    float f11 = (x1 >= 0 && x1 < w && y1 >= 0 && y1 < h) ? 1.f : 0.f;
    float w00 = (wx0*wy0)*f00, w10 = (wx1*wy0)*f10;
    float w01 = (wx0*wy1)*f01, w11 = (wx1*wy1)*f11;

    const float* base = dptr + (size_t)ch * h * w;
    float g00 = __ldg(base + yc0*w + xc0);
    float g10 = __ldg(base + yc0*w + xc1);
    float g01 = __ldg(base + yc1*w + xc0);
    float g11 = __ldg(base + yc1*w + xc1);
    float rv = g00*w00 + g10*w10 + g01*w01 + g11*w11;
    float sq = rv*rv;

    #pragma unroll
    for (int o = 16; o > 0; o >>= 1) sq += __shfl_xor_sync(0xFFFFFFFFu, sq, o);
    int wid = tid >> 5;
    if ((tid & 31) == 0) wsum[wid] = sq;
    __syncthreads();
    float tot = 0.f;
    for (int i = 0; i < nw; i++) tot += wsum[warp0 + i];
    float nrm = fmaxf(sqrtf(tot), 1e-12f);
    float v = rv / nrm;
    __nv_bfloat16 hi = __float2bfloat16(v);
    g_Xh[(size_t)n * KTOT + tid] = hi;
    g_Xl[(size_t)n * KTOT + tid] = __float2bfloat16(v - __bfloat162float(hi));
}

// ---------------- tensor-core GEMM via mma.sync (bf16 hi/lo, fp32 acc) ----------------
// out[256,4096] = M[256,704] @ X[4096,704]^T + bias
#define BM 64
#define BN 128
#define BK 32
#define ASTR 48   // smem row stride in bf16 elements (96B, 16B-aligned)

__device__ __forceinline__ void mma16816(float c[4],
    uint32_t a0, uint32_t a1, uint32_t a2, uint32_t a3,
    uint32_t b0, uint32_t b1)
{
    asm volatile(
        "mma.sync.aligned.m16n8k16.row.col.f32.bf16.bf16.f32 "
        "{%0,%1,%2,%3}, {%4,%5,%6,%7}, {%8,%9}, {%0,%1,%2,%3};"
        : "+f"(c[0]), "+f"(c[1]), "+f"(c[2]), "+f"(c[3])
        : "r"(a0), "r"(a1), "r"(a2), "r"(a3), "r"(b0), "r"(b1));
}

__global__ void __launch_bounds__(256) k_gemm_mma(float* __restrict__ outDesc)
{
    __shared__ __nv_bfloat16 sAh[BM][ASTR], sAl[BM][ASTR];
    __shared__ __nv_bfloat16 sBh[BN][ASTR], sBl[BN][ASTR];

    int tid = threadIdx.x;
    int wid = tid >> 5, lane = tid & 31;
    int grp = lane >> 2, qid = lane & 3;
    int wm = wid & 1;          // 2 warps over M (32 rows each)
    int wn = wid >> 1;         // 4 warps over N (32 cols each)
    int o0 = blockIdx.y * BM;
    int n0 = blockIdx.x * BN;

    float c[2][4][4];
    #pragma unroll
    for (int mt = 0; mt < 2; mt++)
        #pragma unroll
        for (int nt = 0; nt < 4; nt++)
            #pragma unroll
            for (int r = 0; r < 4; r++) c[mt][nt][r] = 0.f;

    for (int k0 = 0; k0 < KTOT; k0 += BK) {
        // fill A: 64 rows x 4 uint4
        {
            int row = tid >> 2, j = tid & 3;
            *(uint4*)&sAh[row][j*8] = *(const uint4*)(g_Mh + (o0+row)*KTOT + k0 + j*8);
            *(uint4*)&sAl[row][j*8] = *(const uint4*)(g_Ml + (o0+row)*KTOT + k0 + j*8);
        }
        // fill B: 128 rows x 4 uint4 = 512 slots
        #pragma unroll
        for (int r = 0; r < 2; r++) {
            int e = tid + r*256;
            int row = e >> 2, j = e & 3;
            size_t gi = (size_t)(n0+row)*KTOT + k0 + j*8;
            *(uint4*)&sBh[row][j*8] = *(const uint4*)(g_Xh + gi);
            *(uint4*)&sBl[row][j*8] = *(const uint4*)(g_Xl + gi);
        }
        __syncthreads();

        #pragma unroll
        for (int ks = 0; ks < 2; ks++) {
            int kb = ks*16 + qid*2;
            uint32_t ah[2][4], al[2][4];
            #pragma unroll
            for (int mt = 0; mt < 2; mt++) {
                int r0 = wm*32 + mt*16 + grp;
                ah[mt][0] = *(const uint32_t*)&sAh[r0  ][kb  ];
                ah[mt][1] = *(const uint32_t*)&sAh[r0+8][kb  ];
                ah[mt][2] = *(const uint32_t*)&sAh[r0  ][kb+8];
                ah[mt][3] = *(const uint32_t*)&sAh[r0+8][kb+8];
                al[mt][0] = *(const uint32_t*)&sAl[r0  ][kb  ];
                al[mt][1] = *(const uint32_t*)&sAl[r0+8][kb  ];
                al[mt][2] = *(const uint32_t*)&sAl[r0  ][kb+8];
                al[mt][3] = *(const uint32_t*)&sAl[r0+8][kb+8];
            }
            #pragma unroll
            for (int nt = 0; nt < 4; nt++) {
                int nr = wn*32 + nt*8 + grp;
                uint32_t bh0 = *(const uint32_t*)&sBh[nr][kb  ];
                uint32_t bh1 = *(const uint32_t*)&sBh[nr][kb+8];
                uint32_t bl0 = *(const uint32_t*)&sBl[nr][kb  ];
                uint32_t bl1 = *(const uint32_t*)&sBl[nr][kb+8];
                #pragma unroll
                for (int mt = 0; mt < 2; mt++) {
                    mma16816(c[mt][nt], ah[mt][0], ah[mt][1], ah[mt][2], ah[mt][3], bh0, bh1);
                    mma16816(c[mt][nt], ah[mt][0], ah[mt][1], ah[mt][2], ah[mt][3], bl0, bl1);
                    mma16816(c[mt][nt], al[mt][0], al[mt][1], al[mt][2], al[mt][3], bh0, bh1);
                }
            }
        }
        __syncthreads();
    }

    // epilogue
    int b = n0 >> 10;
    int nin = n0 & 1023;
    #pragma unroll
    for (int mt = 0; mt < 2; mt++) {
        int o = o0 + wm*32 + mt*16 + grp;
        float bias0 = g_bias[o];
        float bias8 = g_bias[o+8];
        float* row0 = outDesc + (size_t)(b*256 + o    )*MAXKP + nin;
        float* row8 = outDesc + (size_t)(b*256 + o + 8)*MAXKP + nin;
        #pragma unroll
        for (int nt = 0; nt < 4; nt++) {
            int nc = wn*32 + nt*8 + qid*2;
            float2 v0 = make_float2(c[mt][nt][0] + bias0, c[mt][nt][1] + bias0);
            float2 v8 = make_float2(c[mt][nt][2] + bias8, c[mt][nt][3] + bias8);
            *(float2*)(row0 + nc) = v0;
            *(float2*)(row8 + nc) = v8;
        }
    }
}

// ---------------- launch ----------------
extern "C" void kernel_launch(void* const* d_in, const int* in_sizes, int n_in,
                              void* d_out, int out_size)
{
    const float* scores  = (const float*)d_in[0];
    const float* d1      = (const float*)d_in[1];
    const float* d2      = (const float*)d_in[2];
    const float* d3      = (const float*)d_in[3];
    const float* d4      = (const float*)d_in[4];
    const float* lin0_w  = (const float*)d_in[5];
    const float* lin0_b  = (const float*)d_in[6];
    const float* lin1_w  = (const float*)d_in[7];
    const float* lin1_b  = (const float*)d_in[8];
    const float* lin2_w  = (const float*)d_in[9];
    const float* lin2_b  = (const float*)d_in[10];
    const float* merge_w = (const float*)d_in[11];
    const float* merge_b = (const float*)d_in[12];

    float* out     = (float*)d_out;
    float* outKp   = out;
    float* outSc   = out + BB*MAXKP*2;
    float* outDesc = out + BB*MAXKP*2 + BB*MAXKP;

    dim3 tgrid(WW/TX, HH/TY, BB);

    k_reset<<<(BB*NBUCK + 255)/256, 256>>>();
    k_fold<<<(256*KTOT + 255)/256, 256>>>(merge_w, lin0_w, lin1_w, lin2_w);
    k_foldbias<<<1, 256>>>(merge_w, merge_b, lin0_b, lin1_b, lin2_b);

    k_nms1<<<tgrid, 256>>>(scores);
    k_nms23<0><<<tgrid, 256>>>(scores);
    k_nms23<1><<<tgrid, 256>>>(scores);

    k_select<<<BB, 1024>>>(outKp, outSc);
    k_sample<<<BB*MAXKP, 704>>>(d1, d2, d3, d4);
    k_gemm_mma<<<dim3((BB*MAXKP)/BN, 256/BM), 256>>>(outDesc);
}